// round 1
// baseline (speedup 1.0000x reference)
#include <cuda_runtime.h>
#include <math_constants.h>

#define BB 32
#define NN 1024
#define FF 128
#define DG 64
#define TK 15
#define MTOT 256   // 64 q-dims + 64 k-dims + 128 h-dims

// ---- scratch (static device globals; no allocation allowed) ----
__device__ float g_WT[FF * MTOT];      // transposed combined weights [f][dcomb]
__device__ float g_q  [BB * NN * DG];
__device__ float g_kk [BB * NN * DG];
__device__ float g_h  [BB * NN * FF];
__device__ float g_acc[BB * NN * FF];
__device__ int   g_topk[BB * NN * TK];
__device__ float g_deg [BB * NN];
__device__ float g_dinv[BB * NN];

// ---------------------------------------------------------------------------
// Prep: build WT[f][d] = {Wq[d][f], Wk[d-64][f], Wg[d-128][f]} and init deg=2
// (2 self loops per node: module + GCNConv internal). FF*MTOT == BB*NN == 32768.
// ---------------------------------------------------------------------------
__global__ void k_prep(const float* __restrict__ Wq, const float* __restrict__ Wk,
                       const float* __restrict__ Wg) {
    int idx = blockIdx.x * blockDim.x + threadIdx.x;   // 0..32767
    int f = idx >> 8;
    int d = idx & 255;
    float v;
    if (d < 64)       v = Wq[d * FF + f];
    else if (d < 128) v = Wk[(d - 64) * FF + f];
    else              v = Wg[(d - 128) * FF + f];
    g_WT[f * MTOT + d] = v;
    g_deg[idx] = 2.0f;
}

// ---------------------------------------------------------------------------
// Fused GEMM: C[d][n] = sum_f WT[f][d] * x[b][f][n]  (per batch)
// Tile: 64(m) x 64(n), K split in two 64-chunks. 256 threads, 4x4 per thread.
// Stores into g_q (+bq), g_kk (+bk), g_h  in [node][dim] layout.
// ---------------------------------------------------------------------------
__global__ void __launch_bounds__(256) k_qkh(const float* __restrict__ x,
                                             const float* __restrict__ bq,
                                             const float* __restrict__ bk) {
    __shared__ __align__(16) float As[64][64];   // [k][m]
    __shared__ __align__(16) float Bs[64][64];   // [k][n]
    const int m0 = blockIdx.x * 64;
    const int n0 = blockIdx.y * 64;
    const int b  = blockIdx.z;
    const int tid = threadIdx.x;
    const int tx = tid & 15;    // n quad
    const int ty = tid >> 4;    // m quad

    float acc[4][4] = {};

    for (int kt = 0; kt < FF; kt += 64) {
        __syncthreads();
        for (int idx = tid; idx < 64 * 64; idx += 256) {
            int k = idx >> 6, m = idx & 63;
            As[k][m] = g_WT[(kt + k) * MTOT + m0 + m];
            Bs[k][m] = x[(b * FF + kt + k) * NN + n0 + m];
        }
        __syncthreads();
        #pragma unroll 8
        for (int k = 0; k < 64; k++) {
            float4 a  = *(const float4*)&As[k][ty * 4];
            float4 bb = *(const float4*)&Bs[k][tx * 4];
            acc[0][0] += a.x * bb.x; acc[0][1] += a.x * bb.y; acc[0][2] += a.x * bb.z; acc[0][3] += a.x * bb.w;
            acc[1][0] += a.y * bb.x; acc[1][1] += a.y * bb.y; acc[1][2] += a.y * bb.z; acc[1][3] += a.y * bb.w;
            acc[2][0] += a.z * bb.x; acc[2][1] += a.z * bb.y; acc[2][2] += a.z * bb.z; acc[2][3] += a.z * bb.w;
            acc[3][0] += a.w * bb.x; acc[3][1] += a.w * bb.y; acc[3][2] += a.w * bb.z; acc[3][3] += a.w * bb.w;
        }
    }

    const int d0 = m0 + ty * 4;   // combined dim base (multiple of 4)
    float4 bias = make_float4(0.f, 0.f, 0.f, 0.f);
    if (m0 == 0)       bias = *(const float4*)&bq[d0];
    else if (m0 == 64) bias = *(const float4*)&bk[d0 - 64];

    #pragma unroll
    for (int jj = 0; jj < 4; jj++) {
        int n = n0 + tx * 4 + jj;
        float4 v = make_float4(acc[0][jj] + bias.x, acc[1][jj] + bias.y,
                               acc[2][jj] + bias.z, acc[3][jj] + bias.w);
        long nodeBase = (long)(b * NN + n);
        if (m0 == 0)        *(float4*)&g_q [nodeBase * DG + d0]         = v;
        else if (m0 == 64)  *(float4*)&g_kk[nodeBase * DG + (d0 - 64)]  = v;
        else                *(float4*)&g_h [nodeBase * FF + (d0 - 128)] = v;
    }
}

// ---------------------------------------------------------------------------
// Fused scores + top-15 per source row. Warp per row, 8 rows per block.
// scores[r][m] = q[r] . k[m]  (1/sqrt(DG) scale omitted: top-k invariant).
// Diagonal masked to -inf. Selection: 15 iterations of warp argmax with
// (value desc, index asc) total order — matches jax.lax.top_k tie-breaking.
// Also accumulates in-degree into g_deg via exact float atomics.
// ---------------------------------------------------------------------------
__global__ void __launch_bounds__(256) k_topk() {
    __shared__ float qs[8][DG];
    __shared__ __align__(16) float ks[DG][132];   // transposed k tile, padded
    const int b  = blockIdx.y;
    const int r0 = blockIdx.x * 8;
    const int tid  = threadIdx.x;
    const int lane = tid & 31;
    const int w    = tid >> 5;
    const int r    = r0 + w;

    for (int idx = tid; idx < 8 * DG; idx += 256)
        qs[idx >> 6][idx & 63] = g_q[(b * NN + r0 + (idx >> 6)) * DG + (idx & 63)];

    float sc[32];

    #pragma unroll
    for (int t = 0; t < 8; t++) {
        const int m0 = t * 128;
        __syncthreads();
        for (int idx = tid; idx < 128 * DG; idx += 256) {
            int mm = idx >> 6, d = idx & 63;
            ks[d][mm] = g_kk[(b * NN + m0 + mm) * DG + d];
        }
        __syncthreads();
        float a0 = 0.f, a1 = 0.f, a2 = 0.f, a3 = 0.f;
        #pragma unroll 8
        for (int d = 0; d < DG; d++) {
            float qv = qs[w][d];
            float4 kv = *(const float4*)&ks[d][lane * 4];
            a0 += qv * kv.x; a1 += qv * kv.y; a2 += qv * kv.z; a3 += qv * kv.w;
        }
        const int c0 = m0 + lane * 4;
        sc[t * 4 + 0] = (c0 + 0 == r) ? -CUDART_INF_F : a0;
        sc[t * 4 + 1] = (c0 + 1 == r) ? -CUDART_INF_F : a1;
        sc[t * 4 + 2] = (c0 + 2 == r) ? -CUDART_INF_F : a2;
        sc[t * 4 + 3] = (c0 + 3 == r) ? -CUDART_INF_F : a3;
    }

    float pv = CUDART_INF_F;   // previous selection (value)
    int   pi = -1;             // previous selection (index)
    for (int it = 0; it < TK; it++) {
        float bv = -CUDART_INF_F;
        int   bi = 1 << 30;
        #pragma unroll
        for (int s = 0; s < 32; s++) {
            int col = (s >> 2) * 128 + lane * 4 + (s & 3);
            float v = sc[s];
            bool lt = (v < pv) || (v == pv && col > pi);   // strictly after prev pick
            bool gt = (v > bv) || (v == bv && col < bi);   // better than current best
            if (lt && gt) { bv = v; bi = col; }
        }
        #pragma unroll
        for (int off = 16; off; off >>= 1) {
            float ov = __shfl_xor_sync(0xffffffffu, bv, off);
            int   oi = __shfl_xor_sync(0xffffffffu, bi, off);
            if (ov > bv || (ov == bv && oi < bi)) { bv = ov; bi = oi; }
        }
        pv = bv; pi = bi;
        if (lane == 0) {
            g_topk[(b * NN + r) * TK + it] = bi;
            atomicAdd(&g_deg[b * NN + bi], 1.0f);   // integer-valued: exact
        }
    }
}

// ---------------------------------------------------------------------------
__global__ void k_dinv() {
    int i = blockIdx.x * 256 + threadIdx.x;        // B*N
    g_dinv[i] = rsqrtf(g_deg[i]);                  // deg >= 2 always
}

// acc init = two self-loop edges: 2 * h[n] * dinv[n]^2
__global__ void k_accinit() {
    int i = blockIdx.x * 256 + threadIdx.x;        // B*N*F
    float dv = g_dinv[i >> 7];                     // F == 128
    g_acc[i] = 2.0f * g_h[i] * dv * dv;
}

// Edge scatter: warp per edge, 128 coalesced float atomics each.
__global__ void k_scatter() {
    int gw   = (blockIdx.x * 256 + threadIdx.x) >> 5;   // edge id = (b*N+src)*TK + i
    int lane = threadIdx.x & 31;
    int b    = gw / (NN * TK);
    int rem  = gw - b * NN * TK;
    int src  = rem / TK;
    int tgt  = g_topk[gw];
    float norm = g_dinv[b * NN + src] * g_dinv[b * NN + tgt];
    const float* hp = &g_h  [(long)(b * NN + src) * FF];
    float*       ap = &g_acc[(long)(b * NN + tgt) * FF];
    #pragma unroll
    for (int it = 0; it < 4; it++) {
        int f = lane + it * 32;
        atomicAdd(&ap[f], hp[f] * norm);
    }
}

// out[b][f][n] = acc[b][n][f] + bg[f]   (tiled transpose)
__global__ void k_out(float* __restrict__ out, const float* __restrict__ bg) {
    __shared__ float tile[32][33];
    const int n0 = blockIdx.x * 32, f0 = blockIdx.y * 32, b = blockIdx.z;
    const int tx = threadIdx.x, ty = threadIdx.y;   // 32 x 8
    #pragma unroll
    for (int ii = 0; ii < 4; ii++) {
        int n = n0 + ty + ii * 8;
        tile[ty + ii * 8][tx] = g_acc[(long)(b * NN + n) * FF + f0 + tx];
    }
    __syncthreads();
    #pragma unroll
    for (int ii = 0; ii < 4; ii++) {
        int f = f0 + ty + ii * 8;
        out[(long)(b * FF + f) * NN + n0 + tx] = tile[tx][ty + ii * 8] + bg[f];
    }
}

// ---------------------------------------------------------------------------
extern "C" void kernel_launch(void* const* d_in, const int* in_sizes, int n_in,
                              void* d_out, int out_size) {
    const float* x  = (const float*)d_in[0];
    const float* Wq = (const float*)d_in[1];
    const float* bq = (const float*)d_in[2];
    const float* Wk = (const float*)d_in[3];
    const float* bk = (const float*)d_in[4];
    const float* Wg = (const float*)d_in[5];
    const float* bg = (const float*)d_in[6];
    float* out = (float*)d_out;

    k_prep<<<(FF * MTOT) / 256, 256>>>(Wq, Wk, Wg);
    k_qkh<<<dim3(MTOT / 64, NN / 64, BB), 256>>>(x, bq, bk);
    k_topk<<<dim3(NN / 8, BB), 256>>>();
    k_dinv<<<(BB * NN) / 256, 256>>>();
    k_accinit<<<(BB * NN * FF) / 256, 256>>>();
    k_scatter<<<(BB * NN * TK * 32) / 256, 256>>>();
    k_out<<<dim3(NN / 32, FF / 32, BB), dim3(32, 8)>>>(out, bg);
}

// round 2
// speedup vs baseline: 1.0496x; 1.0496x over previous
#include <cuda_runtime.h>
#include <math_constants.h>

#define BB 32
#define NN 1024
#define FF 128
#define DG 64
#define TK 15
#define MTOT 256   // 64 q-dims + 64 k-dims + 128 h-dims

// ---- scratch (static device globals; no allocation allowed) ----
__device__ float g_WT[FF * MTOT];      // transposed combined weights [f][dcomb]
__device__ float g_q  [BB * NN * DG];
__device__ float g_kk [BB * NN * DG];
__device__ float g_h  [BB * NN * FF];
__device__ float g_acc[BB * NN * FF];
__device__ int   g_topk[BB * NN * TK];
__device__ float g_deg [BB * NN];
__device__ float g_dinv[BB * NN];

// ---------------------------------------------------------------------------
// Prep: build WT[f][d] = {Wq[d][f], Wk[d-64][f], Wg[d-128][f]} and init deg=2
// (2 self loops per node: module + GCNConv internal). FF*MTOT == BB*NN == 32768.
// ---------------------------------------------------------------------------
__global__ void k_prep(const float* __restrict__ Wq, const float* __restrict__ Wk,
                       const float* __restrict__ Wg) {
    int idx = blockIdx.x * blockDim.x + threadIdx.x;   // 0..32767
    int f = idx >> 8;
    int d = idx & 255;
    float v;
    if (d < 64)       v = Wq[d * FF + f];
    else if (d < 128) v = Wk[(d - 64) * FF + f];
    else              v = Wg[(d - 128) * FF + f];
    g_WT[f * MTOT + d] = v;
    g_deg[idx] = 2.0f;
}

// ---------------------------------------------------------------------------
// Fused GEMM: C[d][n] = sum_f WT[f][d] * x[b][f][n]  (per batch)
// Tile: 64(m) x 64(n), K split in two 64-chunks. 256 threads, 4x4 per thread.
// Stores into g_q (+bq), g_kk (+bk), g_h  in [node][dim] layout.
// ---------------------------------------------------------------------------
__global__ void __launch_bounds__(256) k_qkh(const float* __restrict__ x,
                                             const float* __restrict__ bq,
                                             const float* __restrict__ bk) {
    __shared__ __align__(16) float As[64][64];   // [k][m]
    __shared__ __align__(16) float Bs[64][64];   // [k][n]
    const int m0 = blockIdx.x * 64;
    const int n0 = blockIdx.y * 64;
    const int b  = blockIdx.z;
    const int tid = threadIdx.x;
    const int tx = tid & 15;    // n quad
    const int ty = tid >> 4;    // m quad

    float acc[4][4] = {};

    for (int kt = 0; kt < FF; kt += 64) {
        __syncthreads();
        for (int idx = tid; idx < 64 * 64; idx += 256) {
            int k = idx >> 6, m = idx & 63;
            As[k][m] = g_WT[(kt + k) * MTOT + m0 + m];
            Bs[k][m] = x[(b * FF + kt + k) * NN + n0 + m];
        }
        __syncthreads();
        #pragma unroll 8
        for (int k = 0; k < 64; k++) {
            float4 a  = *(const float4*)&As[k][ty * 4];
            float4 bb = *(const float4*)&Bs[k][tx * 4];
            acc[0][0] += a.x * bb.x; acc[0][1] += a.x * bb.y; acc[0][2] += a.x * bb.z; acc[0][3] += a.x * bb.w;
            acc[1][0] += a.y * bb.x; acc[1][1] += a.y * bb.y; acc[1][2] += a.y * bb.z; acc[1][3] += a.y * bb.w;
            acc[2][0] += a.z * bb.x; acc[2][1] += a.z * bb.y; acc[2][2] += a.z * bb.z; acc[2][3] += a.z * bb.w;
            acc[3][0] += a.w * bb.x; acc[3][1] += a.w * bb.y; acc[3][2] += a.w * bb.z; acc[3][3] += a.w * bb.w;
        }
    }

    const int d0 = m0 + ty * 4;   // combined dim base (multiple of 4)
    float4 bias = make_float4(0.f, 0.f, 0.f, 0.f);
    if (m0 == 0)       bias = *(const float4*)&bq[d0];
    else if (m0 == 64) bias = *(const float4*)&bk[d0 - 64];

    #pragma unroll
    for (int jj = 0; jj < 4; jj++) {
        int n = n0 + tx * 4 + jj;
        float4 v = make_float4(acc[0][jj] + bias.x, acc[1][jj] + bias.y,
                               acc[2][jj] + bias.z, acc[3][jj] + bias.w);
        long nodeBase = (long)(b * NN + n);
        if (m0 == 0)        *(float4*)&g_q [nodeBase * DG + d0]         = v;
        else if (m0 == 64)  *(float4*)&g_kk[nodeBase * DG + (d0 - 64)]  = v;
        else                *(float4*)&g_h [nodeBase * FF + (d0 - 128)] = v;
    }
}

// ---------------------------------------------------------------------------
// Fused scores + top-15 per source row. Warp per row, 8 rows per block.
// scores[r][m] = q[r] . k[m]  (1/sqrt(DG) scale omitted: top-k invariant).
// Diagonal masked to -inf. Selection: 15 iterations of warp argmax with
// (value desc, index asc) total order — matches jax.lax.top_k tie-breaking.
// Also accumulates in-degree into g_deg via exact float atomics.
// ---------------------------------------------------------------------------
__global__ void __launch_bounds__(256) k_topk() {
    __shared__ float qs[8][DG];
    __shared__ __align__(16) float ks[DG][132];   // transposed k tile, padded
    const int b  = blockIdx.y;
    const int r0 = blockIdx.x * 8;
    const int tid  = threadIdx.x;
    const int lane = tid & 31;
    const int w    = tid >> 5;
    const int r    = r0 + w;

    for (int idx = tid; idx < 8 * DG; idx += 256)
        qs[idx >> 6][idx & 63] = g_q[(b * NN + r0 + (idx >> 6)) * DG + (idx & 63)];

    float sc[32];

    #pragma unroll
    for (int t = 0; t < 8; t++) {
        const int m0 = t * 128;
        __syncthreads();
        for (int idx = tid; idx < 128 * DG; idx += 256) {
            int mm = idx >> 6, d = idx & 63;
            ks[d][mm] = g_kk[(b * NN + m0 + mm) * DG + d];
        }
        __syncthreads();
        float a0 = 0.f, a1 = 0.f, a2 = 0.f, a3 = 0.f;
        #pragma unroll 8
        for (int d = 0; d < DG; d++) {
            float qv = qs[w][d];
            float4 kv = *(const float4*)&ks[d][lane * 4];
            a0 += qv * kv.x; a1 += qv * kv.y; a2 += qv * kv.z; a3 += qv * kv.w;
        }
        const int c0 = m0 + lane * 4;
        sc[t * 4 + 0] = (c0 + 0 == r) ? -CUDART_INF_F : a0;
        sc[t * 4 + 1] = (c0 + 1 == r) ? -CUDART_INF_F : a1;
        sc[t * 4 + 2] = (c0 + 2 == r) ? -CUDART_INF_F : a2;
        sc[t * 4 + 3] = (c0 + 3 == r) ? -CUDART_INF_F : a3;
    }

    float pv = CUDART_INF_F;   // previous selection (value)
    int   pi = -1;             // previous selection (index)
    for (int it = 0; it < TK; it++) {
        float bv = -CUDART_INF_F;
        int   bi = 1 << 30;
        #pragma unroll
        for (int s = 0; s < 32; s++) {
            int col = (s >> 2) * 128 + lane * 4 + (s & 3);
            float v = sc[s];
            bool lt = (v < pv) || (v == pv && col > pi);   // strictly after prev pick
            bool gt = (v > bv) || (v == bv && col < bi);   // better than current best
            if (lt && gt) { bv = v; bi = col; }
        }
        #pragma unroll
        for (int off = 16; off; off >>= 1) {
            float ov = __shfl_xor_sync(0xffffffffu, bv, off);
            int   oi = __shfl_xor_sync(0xffffffffu, bi, off);
            if (ov > bv || (ov == bv && oi < bi)) { bv = ov; bi = oi; }
        }
        pv = bv; pi = bi;
        if (lane == 0) {
            g_topk[(b * NN + r) * TK + it] = bi;
            atomicAdd(&g_deg[b * NN + bi], 1.0f);   // integer-valued: exact
        }
    }
}

// ---------------------------------------------------------------------------
__global__ void k_dinv() {
    int i = blockIdx.x * 256 + threadIdx.x;        // B*N
    g_dinv[i] = rsqrtf(g_deg[i]);                  // deg >= 2 always
}

// acc init = two self-loop edges: 2 * h[n] * dinv[n]^2
__global__ void k_accinit() {
    int i = blockIdx.x * 256 + threadIdx.x;        // B*N*F
    float dv = g_dinv[i >> 7];                     // F == 128
    g_acc[i] = 2.0f * g_h[i] * dv * dv;
}

// Edge scatter: warp per edge, 128 coalesced float atomics each.
__global__ void k_scatter() {
    int gw   = (blockIdx.x * 256 + threadIdx.x) >> 5;   // edge id = (b*N+src)*TK + i
    int lane = threadIdx.x & 31;
    int b    = gw / (NN * TK);
    int rem  = gw - b * NN * TK;
    int src  = rem / TK;
    int tgt  = g_topk[gw];
    float norm = g_dinv[b * NN + src] * g_dinv[b * NN + tgt];
    const float* hp = &g_h  [(long)(b * NN + src) * FF];
    float*       ap = &g_acc[(long)(b * NN + tgt) * FF];
    #pragma unroll
    for (int it = 0; it < 4; it++) {
        int f = lane + it * 32;
        atomicAdd(&ap[f], hp[f] * norm);
    }
}

// out[b][f][n] = acc[b][n][f] + bg[f]   (tiled transpose)
__global__ void k_out(float* __restrict__ out, const float* __restrict__ bg) {
    __shared__ float tile[32][33];
    const int n0 = blockIdx.x * 32, f0 = blockIdx.y * 32, b = blockIdx.z;
    const int tx = threadIdx.x, ty = threadIdx.y;   // 32 x 8
    #pragma unroll
    for (int ii = 0; ii < 4; ii++) {
        int n = n0 + ty + ii * 8;
        tile[ty + ii * 8][tx] = g_acc[(long)(b * NN + n) * FF + f0 + tx];
    }
    __syncthreads();
    #pragma unroll
    for (int ii = 0; ii < 4; ii++) {
        int f = f0 + ty + ii * 8;
        out[(long)(b * FF + f) * NN + n0 + tx] = tile[tx][ty + ii * 8] + bg[f];
    }
}

// ---------------------------------------------------------------------------
extern "C" void kernel_launch(void* const* d_in, const int* in_sizes, int n_in,
                              void* d_out, int out_size) {
    const float* x  = (const float*)d_in[0];
    const float* Wq = (const float*)d_in[1];
    const float* bq = (const float*)d_in[2];
    const float* Wk = (const float*)d_in[3];
    const float* bk = (const float*)d_in[4];
    const float* Wg = (const float*)d_in[5];
    const float* bg = (const float*)d_in[6];
    float* out = (float*)d_out;

    k_prep<<<(FF * MTOT) / 256, 256>>>(Wq, Wk, Wg);
    k_qkh<<<dim3(MTOT / 64, NN / 64, BB), 256>>>(x, bq, bk);
    k_topk<<<dim3(NN / 8, BB), 256>>>();
    k_dinv<<<(BB * NN) / 256, 256>>>();
    k_accinit<<<(BB * NN * FF) / 256, 256>>>();
    k_scatter<<<(BB * NN * TK * 32) / 256, 256>>>();
    k_out<<<dim3(NN / 32, FF / 32, BB), dim3(32, 8)>>>(out, bg);
}

// round 3
// speedup vs baseline: 1.0509x; 1.0012x over previous
#include <cuda_runtime.h>
#include <math_constants.h>

#define BB 32
#define NN 1024
#define FF 128
#define DG 64
#define TK 15
#define MTOT 256   // 64 q-dims + 64 k-dims + 128 h-dims

// ---- scratch (static device globals; no allocation allowed) ----
__device__ float g_WT[FF * MTOT];      // transposed combined weights [f][dcomb]
__device__ float g_q  [BB * NN * DG];
__device__ float g_kk [BB * NN * DG];
__device__ float g_h  [BB * NN * FF];
__device__ float g_acc[BB * NN * FF];
__device__ int   g_topk[BB * NN * TK];
__device__ float g_deg [BB * NN];
__device__ float g_dinv[BB * NN];

// ---------------------------------------------------------------------------
// Prep: build WT[f][d] = {Wq[d][f], Wk[d-64][f], Wg[d-128][f]} and init deg=2
// (2 self loops per node: module + GCNConv internal). FF*MTOT == BB*NN == 32768.
// ---------------------------------------------------------------------------
__global__ void k_prep(const float* __restrict__ Wq, const float* __restrict__ Wk,
                       const float* __restrict__ Wg) {
    int idx = blockIdx.x * blockDim.x + threadIdx.x;   // 0..32767
    int f = idx >> 8;
    int d = idx & 255;
    float v;
    if (d < 64)       v = Wq[d * FF + f];
    else if (d < 128) v = Wk[(d - 64) * FF + f];
    else              v = Wg[(d - 128) * FF + f];
    g_WT[f * MTOT + d] = v;
    g_deg[idx] = 2.0f;
}

// ---------------------------------------------------------------------------
// Fused GEMM: C[d][n] = sum_f WT[f][d] * x[b][f][n]  (per batch)
// Tile: 64(m) x 64(n), K split in two 64-chunks. 256 threads, 4x4 per thread.
// Stores into g_q (+bq), g_kk (+bk), g_h  in [node][dim] layout.
// ---------------------------------------------------------------------------
__global__ void __launch_bounds__(256) k_qkh(const float* __restrict__ x,
                                             const float* __restrict__ bq,
                                             const float* __restrict__ bk) {
    __shared__ __align__(16) float As[64][64];   // [k][m]
    __shared__ __align__(16) float Bs[64][64];   // [k][n]
    const int m0 = blockIdx.x * 64;
    const int n0 = blockIdx.y * 64;
    const int b  = blockIdx.z;
    const int tid = threadIdx.x;
    const int tx = tid & 15;    // n quad
    const int ty = tid >> 4;    // m quad

    float acc[4][4] = {};

    for (int kt = 0; kt < FF; kt += 64) {
        __syncthreads();
        for (int idx = tid; idx < 64 * 64; idx += 256) {
            int k = idx >> 6, m = idx & 63;
            As[k][m] = g_WT[(kt + k) * MTOT + m0 + m];
            Bs[k][m] = x[(b * FF + kt + k) * NN + n0 + m];
        }
        __syncthreads();
        #pragma unroll 8
        for (int k = 0; k < 64; k++) {
            float4 a  = *(const float4*)&As[k][ty * 4];
            float4 bb = *(const float4*)&Bs[k][tx * 4];
            acc[0][0] += a.x * bb.x; acc[0][1] += a.x * bb.y; acc[0][2] += a.x * bb.z; acc[0][3] += a.x * bb.w;
            acc[1][0] += a.y * bb.x; acc[1][1] += a.y * bb.y; acc[1][2] += a.y * bb.z; acc[1][3] += a.y * bb.w;
            acc[2][0] += a.z * bb.x; acc[2][1] += a.z * bb.y; acc[2][2] += a.z * bb.z; acc[2][3] += a.z * bb.w;
            acc[3][0] += a.w * bb.x; acc[3][1] += a.w * bb.y; acc[3][2] += a.w * bb.z; acc[3][3] += a.w * bb.w;
        }
    }

    const int d0 = m0 + ty * 4;   // combined dim base (multiple of 4)
    float4 bias = make_float4(0.f, 0.f, 0.f, 0.f);
    if (m0 == 0)       bias = *(const float4*)&bq[d0];
    else if (m0 == 64) bias = *(const float4*)&bk[d0 - 64];

    #pragma unroll
    for (int jj = 0; jj < 4; jj++) {
        int n = n0 + tx * 4 + jj;
        float4 v = make_float4(acc[0][jj] + bias.x, acc[1][jj] + bias.y,
                               acc[2][jj] + bias.z, acc[3][jj] + bias.w);
        long nodeBase = (long)(b * NN + n);
        if (m0 == 0)        *(float4*)&g_q [nodeBase * DG + d0]         = v;
        else if (m0 == 64)  *(float4*)&g_kk[nodeBase * DG + (d0 - 64)]  = v;
        else                *(float4*)&g_h [nodeBase * FF + (d0 - 128)] = v;
    }
}

// ---------------------------------------------------------------------------
// Fused scores + top-15 per source row. Warp per row, 8 rows per block.
// scores[r][m] = q[r] . k[m]  (1/sqrt(DG) scale omitted: top-k invariant).
// Diagonal masked to -inf. Selection: 15 iterations of warp argmax with
// (value desc, index asc) total order — matches jax.lax.top_k tie-breaking.
// Also accumulates in-degree into g_deg via exact float atomics.
// ---------------------------------------------------------------------------
__global__ void __launch_bounds__(256) k_topk() {
    __shared__ float qs[8][DG];
    __shared__ __align__(16) float ks[DG][132];   // transposed k tile, padded
    const int b  = blockIdx.y;
    const int r0 = blockIdx.x * 8;
    const int tid  = threadIdx.x;
    const int lane = tid & 31;
    const int w    = tid >> 5;
    const int r    = r0 + w;

    for (int idx = tid; idx < 8 * DG; idx += 256)
        qs[idx >> 6][idx & 63] = g_q[(b * NN + r0 + (idx >> 6)) * DG + (idx & 63)];

    float sc[32];

    #pragma unroll
    for (int t = 0; t < 8; t++) {
        const int m0 = t * 128;
        __syncthreads();
        for (int idx = tid; idx < 128 * DG; idx += 256) {
            int mm = idx >> 6, d = idx & 63;
            ks[d][mm] = g_kk[(b * NN + m0 + mm) * DG + d];
        }
        __syncthreads();
        float a0 = 0.f, a1 = 0.f, a2 = 0.f, a3 = 0.f;
        #pragma unroll 8
        for (int d = 0; d < DG; d++) {
            float qv = qs[w][d];
            float4 kv = *(const float4*)&ks[d][lane * 4];
            a0 += qv * kv.x; a1 += qv * kv.y; a2 += qv * kv.z; a3 += qv * kv.w;
        }
        const int c0 = m0 + lane * 4;
        sc[t * 4 + 0] = (c0 + 0 == r) ? -CUDART_INF_F : a0;
        sc[t * 4 + 1] = (c0 + 1 == r) ? -CUDART_INF_F : a1;
        sc[t * 4 + 2] = (c0 + 2 == r) ? -CUDART_INF_F : a2;
        sc[t * 4 + 3] = (c0 + 3 == r) ? -CUDART_INF_F : a3;
    }

    float pv = CUDART_INF_F;   // previous selection (value)
    int   pi = -1;             // previous selection (index)
    for (int it = 0; it < TK; it++) {
        float bv = -CUDART_INF_F;
        int   bi = 1 << 30;
        #pragma unroll
        for (int s = 0; s < 32; s++) {
            int col = (s >> 2) * 128 + lane * 4 + (s & 3);
            float v = sc[s];
            bool lt = (v < pv) || (v == pv && col > pi);   // strictly after prev pick
            bool gt = (v > bv) || (v == bv && col < bi);   // better than current best
            if (lt && gt) { bv = v; bi = col; }
        }
        #pragma unroll
        for (int off = 16; off; off >>= 1) {
            float ov = __shfl_xor_sync(0xffffffffu, bv, off);
            int   oi = __shfl_xor_sync(0xffffffffu, bi, off);
            if (ov > bv || (ov == bv && oi < bi)) { bv = ov; bi = oi; }
        }
        pv = bv; pi = bi;
        if (lane == 0) {
            g_topk[(b * NN + r) * TK + it] = bi;
            atomicAdd(&g_deg[b * NN + bi], 1.0f);   // integer-valued: exact
        }
    }
}

// ---------------------------------------------------------------------------
__global__ void k_dinv() {
    int i = blockIdx.x * 256 + threadIdx.x;        // B*N
    g_dinv[i] = rsqrtf(g_deg[i]);                  // deg >= 2 always
}

// acc init = two self-loop edges: 2 * h[n] * dinv[n]^2
__global__ void k_accinit() {
    int i = blockIdx.x * 256 + threadIdx.x;        // B*N*F
    float dv = g_dinv[i >> 7];                     // F == 128
    g_acc[i] = 2.0f * g_h[i] * dv * dv;
}

// Edge scatter: warp per edge, 128 coalesced float atomics each.
__global__ void k_scatter() {
    int gw   = (blockIdx.x * 256 + threadIdx.x) >> 5;   // edge id = (b*N+src)*TK + i
    int lane = threadIdx.x & 31;
    int b    = gw / (NN * TK);
    int rem  = gw - b * NN * TK;
    int src  = rem / TK;
    int tgt  = g_topk[gw];
    float norm = g_dinv[b * NN + src] * g_dinv[b * NN + tgt];
    const float* hp = &g_h  [(long)(b * NN + src) * FF];
    float*       ap = &g_acc[(long)(b * NN + tgt) * FF];
    #pragma unroll
    for (int it = 0; it < 4; it++) {
        int f = lane + it * 32;
        atomicAdd(&ap[f], hp[f] * norm);
    }
}

// out[b][f][n] = acc[b][n][f] + bg[f]   (tiled transpose)
__global__ void k_out(float* __restrict__ out, const float* __restrict__ bg) {
    __shared__ float tile[32][33];
    const int n0 = blockIdx.x * 32, f0 = blockIdx.y * 32, b = blockIdx.z;
    const int tx = threadIdx.x, ty = threadIdx.y;   // 32 x 8
    #pragma unroll
    for (int ii = 0; ii < 4; ii++) {
        int n = n0 + ty + ii * 8;
        tile[ty + ii * 8][tx] = g_acc[(long)(b * NN + n) * FF + f0 + tx];
    }
    __syncthreads();
    #pragma unroll
    for (int ii = 0; ii < 4; ii++) {
        int f = f0 + ty + ii * 8;
        out[(long)(b * FF + f) * NN + n0 + tx] = tile[tx][ty + ii * 8] + bg[f];
    }
}

// ---------------------------------------------------------------------------
extern "C" void kernel_launch(void* const* d_in, const int* in_sizes, int n_in,
                              void* d_out, int out_size) {
    const float* x  = (const float*)d_in[0];
    const float* Wq = (const float*)d_in[1];
    const float* bq = (const float*)d_in[2];
    const float* Wk = (const float*)d_in[3];
    const float* bk = (const float*)d_in[4];
    const float* Wg = (const float*)d_in[5];
    const float* bg = (const float*)d_in[6];
    float* out = (float*)d_out;

    k_prep<<<(FF * MTOT) / 256, 256>>>(Wq, Wk, Wg);
    k_qkh<<<dim3(MTOT / 64, NN / 64, BB), 256>>>(x, bq, bk);
    k_topk<<<dim3(NN / 8, BB), 256>>>();
    k_dinv<<<(BB * NN) / 256, 256>>>();
    k_accinit<<<(BB * NN * FF) / 256, 256>>>();
    k_scatter<<<(BB * NN * TK * 32) / 256, 256>>>();
    k_out<<<dim3(NN / 32, FF / 32, BB), dim3(32, 8)>>>(out, bg);
}

// round 4
// speedup vs baseline: 1.8831x; 1.7919x over previous
#include <cuda_runtime.h>
#include <math_constants.h>

#define BB 32
#define NN 1024
#define FF 128
#define DG 64
#define TK 15
#define MTOT 256   // 64 q-dims + 64 k-dims + 128 h-dims
#define NEDGE (BB * NN * TK)

// ---- scratch (static device globals; no allocation allowed) ----
__device__ float g_WT [FF * MTOT];     // transposed combined weights [f][dcomb]
__device__ float g_q  [BB * NN * DG];  // [node][d]
__device__ float g_kkT[BB * DG * NN];  // transposed: [b][d][node]
__device__ float g_h  [BB * NN * FF];
__device__ float g_acc[BB * NN * FF];
__device__ int   g_topk[NEDGE];
__device__ float g_deg [BB * NN];
__device__ float g_dinv[BB * NN];
__device__ int   g_off [BB * NN];      // CSR offsets (global edge index)
__device__ int   g_cur [BB * NN];      // fill cursors
__device__ int   g_esrc[NEDGE];        // CSR edge source (global node id b*NN+src)

// ---------------------------------------------------------------------------
// Prep: build WT[f][d] = {Wq[d][f], Wk[d-64][f], Wg[d-128][f]}; init deg=2
// (module self-loop + GCNConv internal self-loop). FF*MTOT == BB*NN == 32768.
// ---------------------------------------------------------------------------
__global__ void k_prep(const float* __restrict__ Wq, const float* __restrict__ Wk,
                       const float* __restrict__ Wg) {
    int idx = blockIdx.x * blockDim.x + threadIdx.x;   // 0..32767
    int f = idx >> 8;
    int d = idx & 255;
    float v;
    if (d < 64)       v = Wq[d * FF + f];
    else if (d < 128) v = Wk[(d - 64) * FF + f];
    else              v = Wg[(d - 128) * FF + f];
    g_WT[f * MTOT + d] = v;
    g_deg[idx] = 2.0f;
}

// ---------------------------------------------------------------------------
// Fused GEMM: C[d][n] = sum_f WT[f][d] * x[b][f][n]  (per batch)
// q -> g_q [node][d] (+bq);  k -> g_kkT [d][node] (+bk);  h -> g_h [node][f].
// ---------------------------------------------------------------------------
__global__ void __launch_bounds__(256) k_qkh(const float* __restrict__ x,
                                             const float* __restrict__ bq,
                                             const float* __restrict__ bk) {
    __shared__ __align__(16) float As[64][64];   // [k][m]
    __shared__ __align__(16) float Bs[64][64];   // [k][n]
    const int m0 = blockIdx.x * 64;
    const int n0 = blockIdx.y * 64;
    const int b  = blockIdx.z;
    const int tid = threadIdx.x;
    const int tx = tid & 15;    // n quad
    const int ty = tid >> 4;    // m quad

    float acc[4][4] = {};

    for (int kt = 0; kt < FF; kt += 64) {
        __syncthreads();
        for (int idx = tid; idx < 64 * 64; idx += 256) {
            int k = idx >> 6, m = idx & 63;
            As[k][m] = g_WT[(kt + k) * MTOT + m0 + m];
            Bs[k][m] = x[(b * FF + kt + k) * NN + n0 + m];
        }
        __syncthreads();
        #pragma unroll 8
        for (int k = 0; k < 64; k++) {
            float4 a  = *(const float4*)&As[k][ty * 4];
            float4 bb = *(const float4*)&Bs[k][tx * 4];
            acc[0][0] += a.x * bb.x; acc[0][1] += a.x * bb.y; acc[0][2] += a.x * bb.z; acc[0][3] += a.x * bb.w;
            acc[1][0] += a.y * bb.x; acc[1][1] += a.y * bb.y; acc[1][2] += a.y * bb.z; acc[1][3] += a.y * bb.w;
            acc[2][0] += a.z * bb.x; acc[2][1] += a.z * bb.y; acc[2][2] += a.z * bb.z; acc[2][3] += a.z * bb.w;
            acc[3][0] += a.w * bb.x; acc[3][1] += a.w * bb.y; acc[3][2] += a.w * bb.z; acc[3][3] += a.w * bb.w;
        }
    }

    const int d0 = m0 + ty * 4;   // combined dim base (multiple of 4)
    float4 bias = make_float4(0.f, 0.f, 0.f, 0.f);
    if (m0 == 0)       bias = *(const float4*)&bq[d0];
    else if (m0 == 64) bias = *(const float4*)&bk[d0 - 64];

    if (m0 == 64) {
        // k part: store transposed rows [d][n], float4 along n
        float bb4[4] = {bias.x, bias.y, bias.z, bias.w};
        #pragma unroll
        for (int i = 0; i < 4; i++) {
            int dd = d0 - 64 + i;
            float4 v = make_float4(acc[i][0] + bb4[i], acc[i][1] + bb4[i],
                                   acc[i][2] + bb4[i], acc[i][3] + bb4[i]);
            *(float4*)&g_kkT[((long)(b * DG + dd)) * NN + n0 + tx * 4] = v;
        }
    } else {
        #pragma unroll
        for (int jj = 0; jj < 4; jj++) {
            int n = n0 + tx * 4 + jj;
            float4 v = make_float4(acc[0][jj] + bias.x, acc[1][jj] + bias.y,
                                   acc[2][jj] + bias.z, acc[3][jj] + bias.w);
            long nodeBase = (long)(b * NN + n);
            if (m0 == 0) *(float4*)&g_q[nodeBase * DG + d0]         = v;
            else         *(float4*)&g_h[nodeBase * FF + (d0 - 128)] = v;
        }
    }
}

// ---------------------------------------------------------------------------
// Top-15 selection from 32 per-lane scores. Per-lane top-2 prefilter, then 15
// warp-argmax extractions with (value desc, index asc) order matching
// jax.lax.top_k. Full per-lane rescan only when a lane yields its 3rd+ value.
// ---------------------------------------------------------------------------
__device__ __forceinline__ void select15(float (&sc)[32], int lane, int b, int r) {
    const float NEG = -CUDART_INF_F;
    const int BIGI = 1 << 30;
    float b1v = NEG; int b1i = BIGI;
    float b2v = NEG; int b2i = BIGI;
    #pragma unroll
    for (int s = 0; s < 32; s++) {
        int col = (s >> 2) * 128 + lane * 4 + (s & 3);   // increasing in s
        float v = sc[s];
        if (v > b1v)      { b2v = b1v; b2i = b1i; b1v = v; b1i = col; }
        else if (v > b2v) { b2v = v; b2i = col; }
    }
    float lv = CUDART_INF_F; int li = -1;    // lane's last extracted (exclusion bound)
    float cv = b1v; int ci = b1i;            // candidate
    float sv = b2v; int si = b2i;            // spare
    for (int it = 0; it < TK; it++) {
        float mv = cv; int mi = ci;
        #pragma unroll
        for (int off = 16; off; off >>= 1) {
            float ov = __shfl_xor_sync(0xffffffffu, mv, off);
            int   oi = __shfl_xor_sync(0xffffffffu, mi, off);
            if (ov > mv || (ov == mv && oi < mi)) { mv = ov; mi = oi; }
        }
        if (lane == 0) {
            g_topk[(b * NN + r) * TK + it] = mi;
            atomicAdd(&g_deg[b * NN + mi], 1.0f);   // integer-valued: exact
        }
        if (ci == mi) {                      // unique owner
            lv = mv; li = mi;
            cv = sv; ci = si; sv = NEG; si = BIGI;
        }
        bool need = (ci == BIGI);
        if (__any_sync(0xffffffffu, need)) {
            if (need) {
                cv = NEG; ci = BIGI;
                #pragma unroll
                for (int s = 0; s < 32; s++) {
                    int col = (s >> 2) * 128 + lane * 4 + (s & 3);
                    float v = sc[s];
                    bool after  = (v < lv) || (v == lv && col > li);
                    bool better = (v > cv) || (v == cv && col < ci);
                    if (after && better) { cv = v; ci = col; }
                }
            }
        }
    }
}

// ---------------------------------------------------------------------------
// Fused scores + top-15. Warp handles 2 rows (kv LDS.128 feeds 8 FMAs),
// 8 warps/block = 16 rows. k-tile from g_kkT: coalesced fill, conflict-free.
// 1/sqrt(DG) scale omitted (top-k invariant). Diagonal masked to -inf.
// ---------------------------------------------------------------------------
__global__ void __launch_bounds__(256) k_topk() {
    __shared__ float qs[16][DG];
    __shared__ __align__(16) float ks[DG][132];   // rows padded: 132*4B keeps 16B align
    const int b  = blockIdx.y;
    const int r0 = blockIdx.x * 16;
    const int tid  = threadIdx.x;
    const int lane = tid & 31;
    const int w    = tid >> 5;
    const int rA = r0 + 2 * w;
    const int rB = rA + 1;

    for (int idx = tid; idx < 16 * DG; idx += 256)
        qs[idx >> 6][idx & 63] = g_q[(b * NN + r0 + (idx >> 6)) * DG + (idx & 63)];

    float sc0[32], sc1[32];

    #pragma unroll
    for (int t = 0; t < 8; t++) {
        const int m0 = t * 128;
        __syncthreads();
        for (int u = tid; u < DG * 32; u += 256) {       // 2048 float4 moves
            int d = u >> 5, ms = u & 31;
            float4 v = *(const float4*)&g_kkT[((long)(b * DG + d)) * NN + m0 + ms * 4];
            *(float4*)&ks[d][ms * 4] = v;
        }
        __syncthreads();
        float a00 = 0, a01 = 0, a02 = 0, a03 = 0;
        float a10 = 0, a11 = 0, a12 = 0, a13 = 0;
        #pragma unroll
        for (int d4 = 0; d4 < DG; d4 += 4) {
            float4 q0 = *(const float4*)&qs[2 * w][d4];      // broadcast, 1 wavefront
            float4 q1 = *(const float4*)&qs[2 * w + 1][d4];
            float q0a[4] = {q0.x, q0.y, q0.z, q0.w};
            float q1a[4] = {q1.x, q1.y, q1.z, q1.w};
            #pragma unroll
            for (int j = 0; j < 4; j++) {
                float4 kv = *(const float4*)&ks[d4 + j][lane * 4];
                a00 += q0a[j] * kv.x; a01 += q0a[j] * kv.y;
                a02 += q0a[j] * kv.z; a03 += q0a[j] * kv.w;
                a10 += q1a[j] * kv.x; a11 += q1a[j] * kv.y;
                a12 += q1a[j] * kv.z; a13 += q1a[j] * kv.w;
            }
        }
        const int c0 = m0 + lane * 4;
        sc0[t * 4 + 0] = (c0 + 0 == rA) ? -CUDART_INF_F : a00;
        sc0[t * 4 + 1] = (c0 + 1 == rA) ? -CUDART_INF_F : a01;
        sc0[t * 4 + 2] = (c0 + 2 == rA) ? -CUDART_INF_F : a02;
        sc0[t * 4 + 3] = (c0 + 3 == rA) ? -CUDART_INF_F : a03;
        sc1[t * 4 + 0] = (c0 + 0 == rB) ? -CUDART_INF_F : a10;
        sc1[t * 4 + 1] = (c0 + 1 == rB) ? -CUDART_INF_F : a11;
        sc1[t * 4 + 2] = (c0 + 2 == rB) ? -CUDART_INF_F : a12;
        sc1[t * 4 + 3] = (c0 + 3 == rB) ? -CUDART_INF_F : a13;
    }

    select15(sc0, lane, b, rA);
    select15(sc1, lane, b, rB);
}

// ---------------------------------------------------------------------------
// CSR offsets: per-batch exclusive scan of in-edge counts (deg-2); also dinv
// and cursor init. One block per batch, 1024 threads (Hillis-Steele scan).
// ---------------------------------------------------------------------------
__global__ void __launch_bounds__(1024) k_offs() {
    __shared__ int s[1024];
    const int b = blockIdx.x, n = threadIdx.x, i = b * NN + n;
    float dg = g_deg[i];
    g_dinv[i] = rsqrtf(dg);
    int c = (int)dg - 2;
    s[n] = c;
    __syncthreads();
    for (int off = 1; off < 1024; off <<= 1) {
        int v = (n >= off) ? s[n - off] : 0;
        __syncthreads();
        s[n] += v;
        __syncthreads();
    }
    g_off[i] = b * NN * TK + s[n] - c;   // exclusive
    g_cur[i] = 0;
}

// CSR fill: thread per edge, slot via int atomic cursor.
__global__ void k_fill() {
    int e = blockIdx.x * 256 + threadIdx.x;   // < NEDGE
    int bnsrc = e / TK;                       // b*NN + src
    int b = bnsrc >> 10;
    int tgt = g_topk[e];
    int bt = (b << 10) + tgt;
    int pos = atomicAdd(&g_cur[bt], 1);
    g_esrc[g_off[bt] + pos] = bnsrc;
}

// ---------------------------------------------------------------------------
// Gather: block per target node, 128 threads (one per feature). Coalesced
// 512B row reads of h[src], register accumulate, single store. No fp atomics.
// out_row = dinv[t] * ( sum_e h[src]*dinv[src] + 2*dinv[t]*h[t] )
// ---------------------------------------------------------------------------
__global__ void __launch_bounds__(128) k_gather() {
    const int t = blockIdx.x;        // global node id b*NN+n
    const int f = threadIdx.x;
    const float dt = g_dinv[t];
    const int cnt = (int)g_deg[t] - 2;
    const int off = g_off[t];
    float acc = 2.0f * dt * g_h[(long)t * FF + f];
    int j = 0;
    for (; j + 4 <= cnt; j += 4) {
        int s0 = g_esrc[off + j],     s1 = g_esrc[off + j + 1];
        int s2 = g_esrc[off + j + 2], s3 = g_esrc[off + j + 3];
        float e0 = g_dinv[s0], e1 = g_dinv[s1], e2 = g_dinv[s2], e3 = g_dinv[s3];
        float h0 = g_h[(long)s0 * FF + f], h1 = g_h[(long)s1 * FF + f];
        float h2 = g_h[(long)s2 * FF + f], h3 = g_h[(long)s3 * FF + f];
        acc += h0 * e0; acc += h1 * e1; acc += h2 * e2; acc += h3 * e3;
    }
    for (; j < cnt; j++) {
        int s = g_esrc[off + j];
        acc += g_h[(long)s * FF + f] * g_dinv[s];
    }
    g_acc[(long)t * FF + f] = acc * dt;
}

// out[b][f][n] = acc[b][n][f] + bg[f]   (tiled transpose)
__global__ void k_out(float* __restrict__ out, const float* __restrict__ bg) {
    __shared__ float tile[32][33];
    const int n0 = blockIdx.x * 32, f0 = blockIdx.y * 32, b = blockIdx.z;
    const int tx = threadIdx.x, ty = threadIdx.y;   // 32 x 8
    #pragma unroll
    for (int ii = 0; ii < 4; ii++) {
        int n = n0 + ty + ii * 8;
        tile[ty + ii * 8][tx] = g_acc[(long)(b * NN + n) * FF + f0 + tx];
    }
    __syncthreads();
    #pragma unroll
    for (int ii = 0; ii < 4; ii++) {
        int f = f0 + ty + ii * 8;
        out[(long)(b * FF + f) * NN + n0 + tx] = tile[tx][ty + ii * 8] + bg[f];
    }
}

// ---------------------------------------------------------------------------
extern "C" void kernel_launch(void* const* d_in, const int* in_sizes, int n_in,
                              void* d_out, int out_size) {
    const float* x  = (const float*)d_in[0];
    const float* Wq = (const float*)d_in[1];
    const float* bq = (const float*)d_in[2];
    const float* Wk = (const float*)d_in[3];
    const float* bk = (const float*)d_in[4];
    const float* Wg = (const float*)d_in[5];
    const float* bg = (const float*)d_in[6];
    float* out = (float*)d_out;

    k_prep<<<(FF * MTOT) / 256, 256>>>(Wq, Wk, Wg);
    k_qkh<<<dim3(MTOT / 64, NN / 64, BB), 256>>>(x, bq, bk);
    k_topk<<<dim3(NN / 16, BB), 256>>>();
    k_offs<<<BB, 1024>>>();
    k_fill<<<NEDGE / 256, 256>>>();
    k_gather<<<BB * NN, 128>>>();
    k_out<<<dim3(NN / 32, FF / 32, BB), dim3(32, 8)>>>(out, bg);
}